// round 1
// baseline (speedup 1.0000x reference)
#include <cuda_runtime.h>
#include <cuda_fp16.h>
#include <cstdint>

#define M_TOK 2048
#define K_IN  4096
#define N_OUT 11008
#define NPACK 1376      // N_OUT / 8
#define GSIZE 128

// Scratch: fp16 activations and fp16 dequantized weights (static device globals;
// no runtime allocation).
__device__ __align__(256) __half g_xh[(size_t)M_TOK * K_IN];          // 16 MB
__device__ __align__(256) __half g_wh[(size_t)K_IN * N_OUT];          // 86 MB

// ---------------------------------------------------------------------------
// Kernel 1: convert x (fp32) -> fp16.  One thread per 8 elements.
// ---------------------------------------------------------------------------
__global__ void k_convert_x(const float* __restrict__ x) {
    int i = blockIdx.x * blockDim.x + threadIdx.x;   // 0 .. M*K/8-1 (exact)
    const float4* p = reinterpret_cast<const float4*>(x) + (size_t)i * 2;
    float4 v0 = p[0], v1 = p[1];
    __half2 h0 = __floats2half2_rn(v0.x, v0.y);
    __half2 h1 = __floats2half2_rn(v0.z, v0.w);
    __half2 h2 = __floats2half2_rn(v1.x, v1.y);
    __half2 h3 = __floats2half2_rn(v1.z, v1.w);
    uint4 o;
    o.x = *reinterpret_cast<unsigned*>(&h0);
    o.y = *reinterpret_cast<unsigned*>(&h1);
    o.z = *reinterpret_cast<unsigned*>(&h2);
    o.w = *reinterpret_cast<unsigned*>(&h3);
    reinterpret_cast<uint4*>(g_xh)[i] = o;
}

// ---------------------------------------------------------------------------
// Kernel 2: dequantize packed int4 weights -> fp16 [K_IN, N_OUT].
// One thread per packed int32 (8 output columns).
// ---------------------------------------------------------------------------
__global__ void k_dequant(const int* __restrict__ qw,
                          const int* __restrict__ qz,
                          const float* __restrict__ sc) {
    int c = blockIdx.x * blockDim.x + threadIdx.x;
    int k = blockIdx.y;
    if (c >= NPACK) return;
    int g = k >> 7;                                  // k / GSIZE
    unsigned q  = (unsigned)qw[(size_t)k * NPACK + c];
    unsigned zq = (unsigned)qz[(size_t)g * NPACK + c];
    const float4* sp = reinterpret_cast<const float4*>(sc + (size_t)g * N_OUT + c * 8);
    float4 s0 = sp[0], s1 = sp[1];
    float sv[8] = {s0.x, s0.y, s0.z, s0.w, s1.x, s1.y, s1.z, s1.w};
    __half h[8];
#pragma unroll
    for (int j = 0; j < 8; j++) {
        int w = (int)((q  >> (4 * j)) & 15u);
        int z = (int)((zq >> (4 * j)) & 15u);
        h[j] = __float2half_rn((float)(w - z) * sv[j]);
    }
    *reinterpret_cast<uint4*>(&g_wh[(size_t)k * N_OUT + c * 8]) =
        *reinterpret_cast<uint4*>(h);
}

// ---------------------------------------------------------------------------
// Kernel 3: fp16 GEMM with fp32 accumulation, mma.sync.m16n8k16.
// Block tile 128x128x32, 256 threads (8 warps = 4m x 2n), cp.async double buffer.
// ---------------------------------------------------------------------------
#define BM 128
#define BN 128
#define BK 32
#define PA 40                       // A smem pitch (halves): conflict-free ldmatrix
#define PB 136                      // B smem pitch (halves)
#define ASTRIDE (BM * PA)           // 5120
#define BSTRIDE (BK * PB)           // 4352
#define STAGE   (ASTRIDE + BSTRIDE) // 9472 halves

__device__ __forceinline__ unsigned smem_u32(const void* p) {
    return (unsigned)__cvta_generic_to_shared(p);
}

__global__ __launch_bounds__(256, 1)
void k_gemm(const float* __restrict__ bias, float* __restrict__ out) {
    __shared__ __align__(16) __half sm[2 * STAGE];

    const int tid  = threadIdx.x;
    const int bm   = blockIdx.y;
    const int bn   = blockIdx.x;
    const int warp = tid >> 5;
    const int lane = tid & 31;
    const int wm   = warp & 3;    // 0..3 : 32-row slice
    const int wn   = warp >> 2;   // 0..1 : 64-col slice

    const __half* gA = g_xh + (size_t)bm * BM * K_IN;
    const __half* gB = g_wh + (size_t)bn * BN;

    auto load_stage = [&](int kt, int s) {
        __half* As = sm + s * STAGE;
        __half* Bs = As + ASTRIDE;
#pragma unroll
        for (int r = 0; r < 2; r++) {               // A: 512 x 16B chunks
            int ch  = tid + r * 256;
            int row = ch >> 2, cc = ch & 3;
            const __half* src = gA + (size_t)row * K_IN + kt * BK + cc * 8;
            unsigned dst = smem_u32(As + row * PA + cc * 8);
            asm volatile("cp.async.cg.shared.global [%0], [%1], 16;\n"
                         :: "r"(dst), "l"(src));
        }
#pragma unroll
        for (int r = 0; r < 2; r++) {               // B: 512 x 16B chunks
            int ch  = tid + r * 256;
            int row = ch >> 4, cc = ch & 15;
            const __half* src = gB + (size_t)(kt * BK + row) * N_OUT + cc * 8;
            unsigned dst = smem_u32(Bs + row * PB + cc * 8);
            asm volatile("cp.async.cg.shared.global [%0], [%1], 16;\n"
                         :: "r"(dst), "l"(src));
        }
        asm volatile("cp.async.commit_group;\n");
    };

    float acc[2][8][4];
#pragma unroll
    for (int i = 0; i < 2; i++)
#pragma unroll
        for (int j = 0; j < 8; j++)
#pragma unroll
            for (int l = 0; l < 4; l++) acc[i][j][l] = 0.0f;

    const int KT = K_IN / BK;   // 128
    load_stage(0, 0);

    for (int kt = 0; kt < KT; kt++) {
        if (kt + 1 < KT) {
            load_stage(kt + 1, (kt + 1) & 1);
            asm volatile("cp.async.wait_group 1;\n");
        } else {
            asm volatile("cp.async.wait_group 0;\n");
        }
        __syncthreads();

        __half* As = sm + (kt & 1) * STAGE;
        __half* Bs = As + ASTRIDE;

        const int mat = lane >> 3;      // which 8x8 of the x4 this lane addresses
        const int lr  = lane & 7;

#pragma unroll
        for (int ks = 0; ks < 2; ks++) {            // two k16 steps per BK=32
            unsigned a[2][4], b[4][4];
#pragma unroll
            for (int mt = 0; mt < 2; mt++) {
                int row = wm * 32 + mt * 16 + (mat & 1) * 8 + lr;
                int col = ks * 16 + (mat >> 1) * 8;
                unsigned addr = smem_u32(As + row * PA + col);
                asm volatile(
                    "ldmatrix.sync.aligned.m8n8.x4.shared.b16 {%0,%1,%2,%3}, [%4];\n"
                    : "=r"(a[mt][0]), "=r"(a[mt][1]), "=r"(a[mt][2]), "=r"(a[mt][3])
                    : "r"(addr));
            }
#pragma unroll
            for (int nb = 0; nb < 4; nb++) {
                int row = ks * 16 + (mat & 1) * 8 + lr;
                int col = wn * 64 + nb * 16 + (mat >> 1) * 8;
                unsigned addr = smem_u32(Bs + row * PB + col);
                asm volatile(
                    "ldmatrix.sync.aligned.m8n8.x4.trans.shared.b16 {%0,%1,%2,%3}, [%4];\n"
                    : "=r"(b[nb][0]), "=r"(b[nb][1]), "=r"(b[nb][2]), "=r"(b[nb][3])
                    : "r"(addr));
            }
#pragma unroll
            for (int mt = 0; mt < 2; mt++)
#pragma unroll
                for (int nt = 0; nt < 8; nt++) {
                    unsigned b0 = b[nt >> 1][(nt & 1) * 2];
                    unsigned b1 = b[nt >> 1][(nt & 1) * 2 + 1];
                    float* d = acc[mt][nt];
                    asm volatile(
                        "mma.sync.aligned.m16n8k16.row.col.f32.f16.f16.f32 "
                        "{%0,%1,%2,%3},{%4,%5,%6,%7},{%8,%9},{%0,%1,%2,%3};\n"
                        : "+f"(d[0]), "+f"(d[1]), "+f"(d[2]), "+f"(d[3])
                        : "r"(a[mt][0]), "r"(a[mt][1]), "r"(a[mt][2]), "r"(a[mt][3]),
                          "r"(b0), "r"(b1));
                }
        }
        __syncthreads();
    }

    // Epilogue: add bias, store fp32.
#pragma unroll
    for (int nt = 0; nt < 8; nt++) {
        int col = bn * BN + wn * 64 + nt * 8 + (lane & 3) * 2;
        float2 bv = *reinterpret_cast<const float2*>(bias + col);
#pragma unroll
        for (int mt = 0; mt < 2; mt++) {
            int row = bm * BM + wm * 32 + mt * 16 + (lane >> 2);
            float2 o0 = make_float2(acc[mt][nt][0] + bv.x, acc[mt][nt][1] + bv.y);
            float2 o1 = make_float2(acc[mt][nt][2] + bv.x, acc[mt][nt][3] + bv.y);
            *reinterpret_cast<float2*>(out + (size_t)row * N_OUT + col)       = o0;
            *reinterpret_cast<float2*>(out + (size_t)(row + 8) * N_OUT + col) = o1;
        }
    }
}

// ---------------------------------------------------------------------------
// Launch
// ---------------------------------------------------------------------------
extern "C" void kernel_launch(void* const* d_in, const int* in_sizes, int n_in,
                              void* d_out, int out_size) {
    const float* x    = (const float*)d_in[0];
    const int*   qw   = (const int*)d_in[1];
    const int*   qz   = (const int*)d_in[2];
    const float* sc   = (const float*)d_in[3];
    const float* bias = (const float*)d_in[4];
    float* out = (float*)d_out;

    // 1) x -> fp16
    k_convert_x<<<(M_TOK * K_IN / 8) / 256, 256>>>(x);

    // 2) dequant weights -> fp16
    dim3 gdq((NPACK + 255) / 256, K_IN);
    k_dequant<<<gdq, 256>>>(qw, qz, sc);

    // 3) GEMM
    dim3 grid(N_OUT / BN, M_TOK / BM);   // (86, 16)
    k_gemm<<<grid, 256>>>(bias, out);
}

// round 6
// speedup vs baseline: 1.3010x; 1.3010x over previous
#include <cuda_runtime.h>
#include <cuda_fp16.h>
#include <cstdint>

#define M_TOK 2048
#define K_IN  4096
#define N_OUT 11008
#define NPACK 1376
#define GSIZE 128

// Scratch (static device globals; no runtime allocation)
__device__ __align__(256) __half g_xh[(size_t)M_TOK * K_IN];          // [M,K] 16 MB
__device__ __align__(256) __half g_wh[(size_t)K_IN * N_OUT];          // [K,N] 86 MB

// ---------------------------------------------------------------------------
// Kernel 1: x fp32 -> fp16
// ---------------------------------------------------------------------------
__global__ void k_convert_x(const float* __restrict__ x) {
    int i = blockIdx.x * blockDim.x + threadIdx.x;
    const float4* p = reinterpret_cast<const float4*>(x) + (size_t)i * 2;
    float4 v0 = p[0], v1 = p[1];
    __half2 h0 = __floats2half2_rn(v0.x, v0.y);
    __half2 h1 = __floats2half2_rn(v0.z, v0.w);
    __half2 h2 = __floats2half2_rn(v1.x, v1.y);
    __half2 h3 = __floats2half2_rn(v1.z, v1.w);
    uint4 o;
    o.x = *reinterpret_cast<unsigned*>(&h0);
    o.y = *reinterpret_cast<unsigned*>(&h1);
    o.z = *reinterpret_cast<unsigned*>(&h2);
    o.w = *reinterpret_cast<unsigned*>(&h3);
    reinterpret_cast<uint4*>(g_xh)[i] = o;
}

// ---------------------------------------------------------------------------
// Kernel 2: dequantize packed int4 -> fp16 [K_IN, N_OUT] row-major.
// ---------------------------------------------------------------------------
__global__ void k_dequant(const int* __restrict__ qw,
                          const int* __restrict__ qz,
                          const float* __restrict__ sc) {
    int c = blockIdx.x * blockDim.x + threadIdx.x;
    int k = blockIdx.y;
    if (c >= NPACK) return;
    int g = k >> 7;
    unsigned q  = (unsigned)qw[(size_t)k * NPACK + c];
    unsigned zq = (unsigned)qz[(size_t)g * NPACK + c];
    const float4* sp = reinterpret_cast<const float4*>(sc + (size_t)g * N_OUT + c * 8);
    float4 s0 = sp[0], s1 = sp[1];
    float sv[8] = {s0.x, s0.y, s0.z, s0.w, s1.x, s1.y, s1.z, s1.w};
    __half h[8];
#pragma unroll
    for (int j = 0; j < 8; j++) {
        int w = (int)((q  >> (4 * j)) & 15u);
        int z = (int)((zq >> (4 * j)) & 15u);
        h[j] = __float2half_rn((float)(w - z) * sv[j]);
    }
    *reinterpret_cast<uint4*>(&g_wh[(size_t)k * N_OUT + c * 8]) =
        *reinterpret_cast<uint4*>(h);
}

// ---------------------------------------------------------------------------
// Kernel 3: fp16 GEMM, mma.sync.m16n8k16, 4-stage cp.async multistage,
// register fragment double-buffering. BM=128 BN=128 BK=64, 256 threads.
// ---------------------------------------------------------------------------
#define BM 128
#define BN 128
#define BK 64
#define NSTAGES 4
#define KT (K_IN / BK)              // 64
#define PA 72                       // A pitch (halves): 144B, conflict-free
#define PB 136                      // B pitch (halves): 272B, conflict-free
#define ASTRIDE (BM * PA)           // 9216 halves
#define BSTRIDE (BK * PB)           // 8704 halves
#define STAGE   (ASTRIDE + BSTRIDE) // 17920 halves = 35840 B
#define SMEM_BYTES (NSTAGES * STAGE * 2)   // 143360 B

__device__ __forceinline__ unsigned smem_u32(const void* p) {
    return (unsigned)__cvta_generic_to_shared(p);
}

__global__ __launch_bounds__(256, 1)
void k_gemm(const float* __restrict__ bias, float* __restrict__ out) {
    extern __shared__ __align__(16) __half sm[];

    const int tid  = threadIdx.x;
    const int bm   = blockIdx.x;       // 16 m-tiles (fast dim: wave shares B)
    const int bn   = blockIdx.y;       // 86 n-tiles
    const int warp = tid >> 5;
    const int lane = tid & 31;
    const int wm   = warp & 3;
    const int wn   = warp >> 2;
    const int mat  = lane >> 3;
    const int lr   = lane & 7;

    const __half* gA = g_xh + (size_t)bm * BM * K_IN;
    const __half* gB = g_wh + (size_t)bn * BN;

    auto load_stage = [&](int kt, int s) {
        __half* As = sm + s * STAGE;
        __half* Bs = As + ASTRIDE;
#pragma unroll
        for (int r = 0; r < 4; r++) {               // A: 1024 chunks of 16B
            int ch  = tid + r * 256;
            int row = ch >> 3, cc = ch & 7;
            const __half* src = gA + (size_t)row * K_IN + kt * BK + cc * 8;
            unsigned dst = smem_u32(As + row * PA + cc * 8);
            asm volatile("cp.async.cg.shared.global [%0], [%1], 16;\n"
                         :: "r"(dst), "l"(src));
        }
#pragma unroll
        for (int r = 0; r < 4; r++) {               // B: 1024 chunks of 16B
            int ch  = tid + r * 256;
            int row = ch >> 4, cc = ch & 15;
            const __half* src = gB + (size_t)(kt * BK + row) * N_OUT + cc * 8;
            unsigned dst = smem_u32(Bs + row * PB + cc * 8);
            asm volatile("cp.async.cg.shared.global [%0], [%1], 16;\n"
                         :: "r"(dst), "l"(src));
        }
        asm volatile("cp.async.commit_group;\n");
    };

    float acc[2][8][4];
#pragma unroll
    for (int i = 0; i < 2; i++)
#pragma unroll
        for (int j = 0; j < 8; j++)
#pragma unroll
            for (int l = 0; l < 4; l++) acc[i][j][l] = 0.0f;

    // Prologue: fill NSTAGES-1 stages
    load_stage(0, 0);
    load_stage(1, 1);
    load_stage(2, 2);

    for (int kt = 0; kt < KT; kt++) {
        asm volatile("cp.async.wait_group 2;\n");
        __syncthreads();

        // Issue next stage (slot freed last iteration); empty commit keeps
        // group accounting uniform at the tail.
        if (kt + 3 < KT) load_stage(kt + 3, (kt + 3) & (NSTAGES - 1));
        else             asm volatile("cp.async.commit_group;\n");

        __half* As = sm + (kt & (NSTAGES - 1)) * STAGE;
        __half* Bs = As + ASTRIDE;

        unsigned a[2][2][4], b[2][4][4];

        auto ld_frags = [&](int ks, unsigned (*af)[4], unsigned (*bf)[4]) {
#pragma unroll
            for (int mt = 0; mt < 2; mt++) {
                int row = wm * 32 + mt * 16 + (mat & 1) * 8 + lr;
                int col = ks * 16 + (mat >> 1) * 8;
                unsigned addr = smem_u32(As + row * PA + col);
                asm volatile(
                    "ldmatrix.sync.aligned.m8n8.x4.shared.b16 {%0,%1,%2,%3}, [%4];\n"
                    : "=r"(af[mt][0]), "=r"(af[mt][1]), "=r"(af[mt][2]), "=r"(af[mt][3])
                    : "r"(addr));
            }
#pragma unroll
            for (int nb = 0; nb < 4; nb++) {
                int row = ks * 16 + (mat & 1) * 8 + lr;
                int col = wn * 64 + nb * 16 + (mat >> 1) * 8;
                unsigned addr = smem_u32(Bs + row * PB + col);
                asm volatile(
                    "ldmatrix.sync.aligned.m8n8.x4.trans.shared.b16 {%0,%1,%2,%3}, [%4];\n"
                    : "=r"(bf[nb][0]), "=r"(bf[nb][1]), "=r"(bf[nb][2]), "=r"(bf[nb][3])
                    : "r"(addr));
            }
        };

        ld_frags(0, a[0], b[0]);
#pragma unroll
        for (int ks = 0; ks < 4; ks++) {
            if (ks < 3) ld_frags(ks + 1, a[(ks + 1) & 1], b[(ks + 1) & 1]);
            unsigned (*af)[4] = a[ks & 1];
            unsigned (*bf)[4] = b[ks & 1];
#pragma unroll
            for (int mt = 0; mt < 2; mt++)
#pragma unroll
                for (int nt = 0; nt < 8; nt++) {
                    unsigned b0 = bf[nt >> 1][(nt & 1) * 2];
                    unsigned b1 = bf[nt >> 1][(nt & 1) * 2 + 1];
                    float* d = acc[mt][nt];
                    asm volatile(
                        "mma.sync.aligned.m16n8k16.row.col.f32.f16.f16.f32 "
                        "{%0,%1,%2,%3},{%4,%5,%6,%7},{%8,%9},{%0,%1,%2,%3};\n"
                        : "+f"(d[0]), "+f"(d[1]), "+f"(d[2]), "+f"(d[3])
                        : "r"(af[mt][0]), "r"(af[mt][1]), "r"(af[mt][2]), "r"(af[mt][3]),
                          "r"(b0), "r"(b1));
                }
        }
        __syncthreads();
    }

    // Epilogue: add bias, store fp32.
#pragma unroll
    for (int nt = 0; nt < 8; nt++) {
        int col = bn * BN + wn * 64 + nt * 8 + (lane & 3) * 2;
        float2 bv = *reinterpret_cast<const float2*>(bias + col);
#pragma unroll
        for (int mt = 0; mt < 2; mt++) {
            int row = bm * BM + wm * 32 + mt * 16 + (lane >> 2);
            float2 o0 = make_float2(acc[mt][nt][0] + bv.x, acc[mt][nt][1] + bv.y);
            float2 o1 = make_float2(acc[mt][nt][2] + bv.x, acc[mt][nt][3] + bv.y);
            *reinterpret_cast<float2*>(out + (size_t)row * N_OUT + col)       = o0;
            *reinterpret_cast<float2*>(out + (size_t)(row + 8) * N_OUT + col) = o1;
        }
    }
}

// ---------------------------------------------------------------------------
// Launch
// ---------------------------------------------------------------------------
extern "C" void kernel_launch(void* const* d_in, const int* in_sizes, int n_in,
                              void* d_out, int out_size) {
    const float* x    = (const float*)d_in[0];
    const int*   qw   = (const int*)d_in[1];
    const int*   qz   = (const int*)d_in[2];
    const float* sc   = (const float*)d_in[3];
    const float* bias = (const float*)d_in[4];
    float* out = (float*)d_out;

    k_convert_x<<<(M_TOK * K_IN / 8) / 256, 256>>>(x);

    dim3 gdq((NPACK + 255) / 256, K_IN);
    k_dequant<<<gdq, 256>>>(qw, qz, sc);

    static bool attr_set = false;
    if (!attr_set) {
        cudaFuncSetAttribute(k_gemm, cudaFuncAttributeMaxDynamicSharedMemorySize,
                             SMEM_BYTES);
        attr_set = true;
    }
    dim3 grid(M_TOK / BM, N_OUT / BN);   // (16, 86)
    k_gemm<<<grid, 256, SMEM_BYTES>>>(bias, out);
}

// round 9
// speedup vs baseline: 1.5094x; 1.1602x over previous
#include <cuda_runtime.h>
#include <cuda_fp16.h>
#include <cstdint>

#define M_TOK 2048
#define K_IN  4096
#define N_OUT 11008
#define NPACK 1376
#define GSIZE 128

// Scratch (static device globals; no runtime allocation)
__device__ __align__(256) __half g_xh[(size_t)M_TOK * K_IN];          // [M,K] 16 MB
__device__ __align__(256) __half g_wh[(size_t)K_IN * N_OUT];          // [K,N] 86 MB

// ---------------------------------------------------------------------------
// Kernel 1: x fp32 -> fp16
// ---------------------------------------------------------------------------
__global__ void k_convert_x(const float* __restrict__ x) {
    int i = blockIdx.x * blockDim.x + threadIdx.x;
    const float4* p = reinterpret_cast<const float4*>(x) + (size_t)i * 2;
    float4 v0 = p[0], v1 = p[1];
    __half2 h0 = __floats2half2_rn(v0.x, v0.y);
    __half2 h1 = __floats2half2_rn(v0.z, v0.w);
    __half2 h2 = __floats2half2_rn(v1.x, v1.y);
    __half2 h3 = __floats2half2_rn(v1.z, v1.w);
    uint4 o;
    o.x = *reinterpret_cast<unsigned*>(&h0);
    o.y = *reinterpret_cast<unsigned*>(&h1);
    o.z = *reinterpret_cast<unsigned*>(&h2);
    o.w = *reinterpret_cast<unsigned*>(&h3);
    reinterpret_cast<uint4*>(g_xh)[i] = o;
}

// ---------------------------------------------------------------------------
// Kernel 2: dequantize packed int4 -> fp16 [K_IN, N_OUT] row-major.
// ---------------------------------------------------------------------------
__global__ void k_dequant(const int* __restrict__ qw,
                          const int* __restrict__ qz,
                          const float* __restrict__ sc) {
    int c = blockIdx.x * blockDim.x + threadIdx.x;
    int k = blockIdx.y;
    if (c >= NPACK) return;
    int g = k >> 7;
    unsigned q  = (unsigned)qw[(size_t)k * NPACK + c];
    unsigned zq = (unsigned)qz[(size_t)g * NPACK + c];
    const float4* sp = reinterpret_cast<const float4*>(sc + (size_t)g * N_OUT + c * 8);
    float4 s0 = sp[0], s1 = sp[1];
    float sv[8] = {s0.x, s0.y, s0.z, s0.w, s1.x, s1.y, s1.z, s1.w};
    __half h[8];
#pragma unroll
    for (int j = 0; j < 8; j++) {
        int w = (int)((q  >> (4 * j)) & 15u);
        int z = (int)((zq >> (4 * j)) & 15u);
        h[j] = __float2half_rn((float)(w - z) * sv[j]);
    }
    *reinterpret_cast<uint4*>(&g_wh[(size_t)k * N_OUT + c * 8]) =
        *reinterpret_cast<uint4*>(h);
}

// ---------------------------------------------------------------------------
// Kernel 3: fp16 GEMM, mma.sync.m16n8k16, 4-stage cp.async multistage.
// BM=128 BN=256 BK=64, 256 threads, 8 warps (2m x 4n), warp tile 64x64.
// ---------------------------------------------------------------------------
#define BM 128
#define BN 256
#define BK 64
#define NSTAGES 4
#define KT (K_IN / BK)              // 64
#define PA 72                       // A pitch (halves): 144B, conflict-free
#define PB 264                      // B pitch (halves): 528B, conflict-free
#define ASTRIDE (BM * PA)           // 9216 halves
#define BSTRIDE (BK * PB)           // 16896 halves
#define STAGE   (ASTRIDE + BSTRIDE) // 26112 halves = 52224 B
#define SMEM_BYTES (NSTAGES * STAGE * 2)   // 208896 B

__device__ __forceinline__ unsigned smem_u32(const void* p) {
    return (unsigned)__cvta_generic_to_shared(p);
}

__global__ __launch_bounds__(256, 1)
void k_gemm(const float* __restrict__ bias, float* __restrict__ out) {
    extern __shared__ __align__(16) __half sm[];

    const int tid  = threadIdx.x;
    const int bm   = blockIdx.x;       // 16 m-tiles (fast dim: wave shares B)
    const int bn   = blockIdx.y;       // 43 n-tiles
    const int warp = tid >> 5;
    const int lane = tid & 31;
    const int wm   = warp & 1;         // 2 m groups of 64 rows
    const int wn   = warp >> 1;        // 4 n groups of 64 cols
    const int mat  = lane >> 3;
    const int lr   = lane & 7;

    const __half* gA = g_xh + (size_t)bm * BM * K_IN;
    const __half* gB = g_wh + (size_t)bn * BN;

    auto load_stage = [&](int kt, int s) {
        __half* As = sm + s * STAGE;
        __half* Bs = As + ASTRIDE;
#pragma unroll
        for (int r = 0; r < 4; r++) {               // A: 1024 chunks of 16B
            int ch  = tid + r * 256;
            int row = ch >> 3, cc = ch & 7;
            const __half* src = gA + (size_t)row * K_IN + kt * BK + cc * 8;
            unsigned dst = smem_u32(As + row * PA + cc * 8);
            asm volatile("cp.async.cg.shared.global [%0], [%1], 16;\n"
                         :: "r"(dst), "l"(src));
        }
#pragma unroll
        for (int r = 0; r < 8; r++) {               // B: 2048 chunks of 16B
            int ch  = tid + r * 256;
            int row = ch >> 5, cc = ch & 31;
            const __half* src = gB + (size_t)(kt * BK + row) * N_OUT + cc * 8;
            unsigned dst = smem_u32(Bs + row * PB + cc * 8);
            asm volatile("cp.async.cg.shared.global [%0], [%1], 16;\n"
                         :: "r"(dst), "l"(src));
        }
        asm volatile("cp.async.commit_group;\n");
    };

    float acc[4][8][4];
#pragma unroll
    for (int i = 0; i < 4; i++)
#pragma unroll
        for (int j = 0; j < 8; j++)
#pragma unroll
            for (int l = 0; l < 4; l++) acc[i][j][l] = 0.0f;

    // Prologue: fill NSTAGES-1 stages
    load_stage(0, 0);
    load_stage(1, 1);
    load_stage(2, 2);

    for (int kt = 0; kt < KT; kt++) {
        asm volatile("cp.async.wait_group 2;\n");
        __syncthreads();

        if (kt + 3 < KT) load_stage(kt + 3, (kt + 3) & (NSTAGES - 1));
        else             asm volatile("cp.async.commit_group;\n");

        __half* As = sm + (kt & (NSTAGES - 1)) * STAGE;
        __half* Bs = As + ASTRIDE;

        unsigned a[2][4][4], b[2][4][4];

        auto ld_frags = [&](int ks, unsigned (*af)[4], unsigned (*bf)[4]) {
#pragma unroll
            for (int mt = 0; mt < 4; mt++) {
                int row = wm * 64 + mt * 16 + (mat & 1) * 8 + lr;
                int col = ks * 16 + (mat >> 1) * 8;
                unsigned addr = smem_u32(As + row * PA + col);
                asm volatile(
                    "ldmatrix.sync.aligned.m8n8.x4.shared.b16 {%0,%1,%2,%3}, [%4];\n"
                    : "=r"(af[mt][0]), "=r"(af[mt][1]), "=r"(af[mt][2]), "=r"(af[mt][3])
                    : "r"(addr));
            }
#pragma unroll
            for (int nb = 0; nb < 4; nb++) {
                int row = ks * 16 + (mat & 1) * 8 + lr;
                int col = wn * 64 + nb * 16 + (mat >> 1) * 8;
                unsigned addr = smem_u32(Bs + row * PB + col);
                asm volatile(
                    "ldmatrix.sync.aligned.m8n8.x4.trans.shared.b16 {%0,%1,%2,%3}, [%4];\n"
                    : "=r"(bf[nb][0]), "=r"(bf[nb][1]), "=r"(bf[nb][2]), "=r"(bf[nb][3])
                    : "r"(addr));
            }
        };

        ld_frags(0, a[0], b[0]);
#pragma unroll
        for (int ks = 0; ks < 4; ks++) {
            if (ks < 3) ld_frags(ks + 1, a[(ks + 1) & 1], b[(ks + 1) & 1]);
            unsigned (*af)[4] = a[ks & 1];
            unsigned (*bf)[4] = b[ks & 1];
#pragma unroll
            for (int mt = 0; mt < 4; mt++)
#pragma unroll
                for (int nt = 0; nt < 8; nt++) {
                    unsigned b0 = bf[nt >> 1][(nt & 1) * 2];
                    unsigned b1 = bf[nt >> 1][(nt & 1) * 2 + 1];
                    float* d = acc[mt][nt];
                    asm volatile(
                        "mma.sync.aligned.m16n8k16.row.col.f32.f16.f16.f32 "
                        "{%0,%1,%2,%3},{%4,%5,%6,%7},{%8,%9},{%0,%1,%2,%3};\n"
                        : "+f"(d[0]), "+f"(d[1]), "+f"(d[2]), "+f"(d[3])
                        : "r"(af[mt][0]), "r"(af[mt][1]), "r"(af[mt][2]), "r"(af[mt][3]),
                          "r"(b0), "r"(b1));
                }
        }
        __syncthreads();
    }

    // Epilogue: add bias, store fp32.
#pragma unroll
    for (int nt = 0; nt < 8; nt++) {
        int col = bn * BN + wn * 64 + nt * 8 + (lane & 3) * 2;
        float2 bv = *reinterpret_cast<const float2*>(bias + col);
#pragma unroll
        for (int mt = 0; mt < 4; mt++) {
            int row = bm * BM + wm * 64 + mt * 16 + (lane >> 2);
            float2 o0 = make_float2(acc[mt][nt][0] + bv.x, acc[mt][nt][1] + bv.y);
            float2 o1 = make_float2(acc[mt][nt][2] + bv.x, acc[mt][nt][3] + bv.y);
            *reinterpret_cast<float2*>(out + (size_t)row * N_OUT + col)       = o0;
            *reinterpret_cast<float2*>(out + (size_t)(row + 8) * N_OUT + col) = o1;
        }
    }
}

// ---------------------------------------------------------------------------
// Launch
// ---------------------------------------------------------------------------
extern "C" void kernel_launch(void* const* d_in, const int* in_sizes, int n_in,
                              void* d_out, int out_size) {
    const float* x    = (const float*)d_in[0];
    const int*   qw   = (const int*)d_in[1];
    const int*   qz   = (const int*)d_in[2];
    const float* sc   = (const float*)d_in[3];
    const float* bias = (const float*)d_in[4];
    float* out = (float*)d_out;

    k_convert_x<<<(M_TOK * K_IN / 8) / 256, 256>>>(x);

    dim3 gdq((NPACK + 255) / 256, K_IN);
    k_dequant<<<gdq, 256>>>(qw, qz, sc);

    static bool attr_set = false;
    if (!attr_set) {
        cudaFuncSetAttribute(k_gemm, cudaFuncAttributeMaxDynamicSharedMemorySize,
                             SMEM_BYTES);
        attr_set = true;
    }
    dim3 grid(M_TOK / BM, N_OUT / BN);   // (16, 43)
    k_gemm<<<grid, 256, SMEM_BYTES>>>(bias, out);
}